// round 15
// baseline (speedup 1.0000x reference)
#include <cuda_runtime.h>
#include <cuda_fp16.h>
#include <mma.h>

using namespace nvcuda;

#define N_NODES 50000
#define N_EDGES 800000
#define N_LABEL 200000
#define CAP 128            // bucket capacity per node (max deg ~40 for this data)

// ---------------- scratch (device globals; no allocation allowed) ----------
__device__ int    g_cnt[N_NODES];        // zero at load; re-zeroed by decode
__device__ float  g_dis[N_NODES];        // (deg+1)^-1/2 (written by gemm1 epilogue)
__device__ __align__(16) int    g_bkt[N_NODES * CAP];  // per-node edge buckets
__device__ __align__(16) __half g_hh[N_NODES * 128];   // fp16((x@W1) * dis[row])
__device__ __align__(16) __half g_h1[N_NODES * 128];   // relu layer-1 output, fp16
__device__ __align__(16) __half g_zh[N_NODES * 64];    // (h1 @ W2)*dis, fp16
__device__ __align__(16) __half g_zfh[N_NODES * 64];   // final embeddings, fp16

// ---------------- PDL launcher with plain-launch fallback -------------------
template <typename K, typename... A>
static inline void launch_pdl(K kern, dim3 grid, dim3 block, size_t smem, A... args) {
    cudaLaunchConfig_t cfg = {};
    cfg.gridDim = grid; cfg.blockDim = block; cfg.dynamicSmemBytes = smem; cfg.stream = 0;
    cudaLaunchAttribute at[1];
    at[0].id = cudaLaunchAttributeProgrammaticStreamSerialization;
    at[0].val.programmaticStreamSerializationAllowed = 1;
    cfg.attrs = at; cfg.numAttrs = 1;
    if (cudaLaunchKernelEx(&cfg, kern, args...) != cudaSuccess) {
        void* pa[] = { (void*)&args... };
        cudaLaunchKernel((const void*)kern, grid, block, pa, smem, 0);
    }
}

// ---------------- direct bucket fill (8 edges/thread) -----------------------
__global__ void k_fill_direct(const int4* __restrict__ row4,
                              const int4* __restrict__ col4) {
    int i = blockIdx.x * blockDim.x + threadIdx.x;
    if (i >= N_EDGES / 8) return;
    int4 r0 = row4[2 * i], r1 = row4[2 * i + 1];
    int4 c0 = col4[2 * i], c1 = col4[2 * i + 1];
    int p0 = atomicAdd(&g_cnt[c0.x], 1);
    int p1 = atomicAdd(&g_cnt[c0.y], 1);
    int p2 = atomicAdd(&g_cnt[c0.z], 1);
    int p3 = atomicAdd(&g_cnt[c0.w], 1);
    int p4 = atomicAdd(&g_cnt[c1.x], 1);
    int p5 = atomicAdd(&g_cnt[c1.y], 1);
    int p6 = atomicAdd(&g_cnt[c1.z], 1);
    int p7 = atomicAdd(&g_cnt[c1.w], 1);
    if (p0 < CAP) g_bkt[c0.x * CAP + p0] = r0.x;
    if (p1 < CAP) g_bkt[c0.y * CAP + p1] = r0.y;
    if (p2 < CAP) g_bkt[c0.z * CAP + p2] = r0.z;
    if (p3 < CAP) g_bkt[c0.w * CAP + p3] = r0.w;
    if (p4 < CAP) g_bkt[c1.x * CAP + p4] = r1.x;
    if (p5 < CAP) g_bkt[c1.y * CAP + p5] = r1.y;
    if (p6 < CAP) g_bkt[c1.z * CAP + p6] = r1.z;
    if (p7 < CAP) g_bkt[c1.w * CAP + p7] = r1.w;
}

// ---------------- GEMM1 (tensor): Hh = fp16((X @ W1) * dis[row]) ------------
__global__ __launch_bounds__(256) void k_gemm1(const float* __restrict__ X,
                                               const float* __restrict__ W,
                                               __half* __restrict__ Y) {
    constexpr int LDA = 136, LDB = 136;
    extern __shared__ __align__(32) char smem[];
    __half* sA = (__half*)smem;                    // 128*136*2 = 34816
    __half* sB = (__half*)(smem + 34816);          // 128*136*2 = 34816
    float*  sC = (float*)smem;                     // 128*128*4 = 65536 (alias)

    const int tid = threadIdx.x;
    const int wid = tid >> 5;
    const int m0  = blockIdx.x * 128;

    #pragma unroll
    for (int i = tid; i < 128 * 32; i += 256) {
        int r = i >> 5, c4 = i & 31;
        int gr = m0 + r;
        float4 v = (gr < N_NODES) ? ((const float4*)X)[gr * 32 + c4]
                                  : make_float4(0.f, 0.f, 0.f, 0.f);
        __half2 a = __floats2half2_rn(v.x, v.y);
        __half2 b = __floats2half2_rn(v.z, v.w);
        *(uint2*)(sA + r * LDA + c4 * 4) = make_uint2(*(unsigned*)&a, *(unsigned*)&b);
    }
    #pragma unroll
    for (int i = tid; i < 128 * 32; i += 256) {
        int r = i >> 5, c4 = i & 31;
        float4 v = ((const float4*)W)[r * 32 + c4];
        __half2 a = __floats2half2_rn(v.x, v.y);
        __half2 b = __floats2half2_rn(v.z, v.w);
        *(uint2*)(sB + r * LDB + c4 * 4) = make_uint2(*(unsigned*)&a, *(unsigned*)&b);
    }
    __syncthreads();

    wmma::fragment<wmma::accumulator, 16, 16, 16, float> c[8];
    #pragma unroll
    for (int n = 0; n < 8; n++) wmma::fill_fragment(c[n], 0.0f);

    #pragma unroll
    for (int k0 = 0; k0 < 8; k0++) {
        wmma::fragment<wmma::matrix_a, 16, 16, 16, __half, wmma::row_major> a;
        wmma::load_matrix_sync(a, sA + wid * 16 * LDA + k0 * 16, LDA);
        #pragma unroll
        for (int n = 0; n < 8; n++) {
            wmma::fragment<wmma::matrix_b, 16, 16, 16, __half, wmma::row_major> b;
            wmma::load_matrix_sync(b, sB + k0 * 16 * LDB + n * 16, LDB);
            wmma::mma_sync(c[n], a, b, c[n]);
        }
    }
    __syncthreads();

    #pragma unroll
    for (int n = 0; n < 8; n++)
        wmma::store_matrix_sync(sC + wid * 16 * 128 + n * 16, c[n], 128, wmma::mem_row_major);

    cudaGridDependencySynchronize();   // fill done -> g_cnt valid
    __syncthreads();

    #pragma unroll
    for (int i = tid; i < 128 * 16; i += 256) {
        int r = i >> 4, c8 = i & 15;
        int gr = m0 + r;
        if (gr < N_NODES) {
            float s = rsqrtf((float)g_cnt[gr] + 1.0f);
            if (c8 == 0) g_dis[gr] = s;
            const float* p = sC + r * 128 + c8 * 8;
            __half2 h0 = __floats2half2_rn(p[0] * s, p[1] * s);
            __half2 h1 = __floats2half2_rn(p[2] * s, p[3] * s);
            __half2 h2 = __floats2half2_rn(p[4] * s, p[5] * s);
            __half2 h3 = __floats2half2_rn(p[6] * s, p[7] * s);
            *(uint4*)(Y + gr * 128 + c8 * 8) =
                make_uint4(*(unsigned*)&h0, *(unsigned*)&h1, *(unsigned*)&h2, *(unsigned*)&h3);
        }
    }
}

// ---------------- GEMM2 (tensor): Zh = fp16((H1 @ W2) * dis[row]) -----------
__global__ __launch_bounds__(256) void k_gemm2(const __half* __restrict__ X,
                                               const float* __restrict__ W,
                                               __half* __restrict__ Y) {
    constexpr int LDA = 136, LDB = 72;
    extern __shared__ __align__(32) char smem[];
    __half* sA = (__half*)smem;                    // 64*136*2  = 17408
    __half* sB = (__half*)(smem + 17408);          // 128*72*2  = 18432
    float*  sC = (float*)smem;                     // 64*64*4   = 16384 (alias)

    const int tid = threadIdx.x;
    const int wid = tid >> 5;
    const int m0  = blockIdx.x * 64;

    #pragma unroll
    for (int i = tid; i < 128 * 16; i += 256) {
        int r = i >> 4, c4 = i & 15;
        float4 v = ((const float4*)W)[r * 16 + c4];
        __half2 a = __floats2half2_rn(v.x, v.y);
        __half2 b = __floats2half2_rn(v.z, v.w);
        *(uint2*)(sB + r * LDB + c4 * 4) = make_uint2(*(unsigned*)&a, *(unsigned*)&b);
    }

    cudaGridDependencySynchronize();   // wait for agg1's h1

    #pragma unroll
    for (int i = tid; i < 64 * 16; i += 256) {
        int r = i >> 4, c8 = i & 15;
        int gr = m0 + r;
        uint4 v = (gr < N_NODES) ? ((const uint4*)X)[gr * 16 + c8]
                                 : make_uint4(0, 0, 0, 0);
        *(uint4*)(sA + r * LDA + c8 * 8) = v;
    }
    __syncthreads();

    const int rt = wid >> 1;            // 0..3 row tile
    const int cp = (wid & 1) * 2;       // col tiles cp, cp+1

    wmma::fragment<wmma::accumulator, 16, 16, 16, float> c[2];
    #pragma unroll
    for (int n = 0; n < 2; n++) wmma::fill_fragment(c[n], 0.0f);

    #pragma unroll
    for (int k0 = 0; k0 < 8; k0++) {
        wmma::fragment<wmma::matrix_a, 16, 16, 16, __half, wmma::row_major> a;
        wmma::load_matrix_sync(a, sA + rt * 16 * LDA + k0 * 16, LDA);
        #pragma unroll
        for (int n = 0; n < 2; n++) {
            wmma::fragment<wmma::matrix_b, 16, 16, 16, __half, wmma::row_major> b;
            wmma::load_matrix_sync(b, sB + k0 * 16 * LDB + (cp + n) * 16, LDB);
            wmma::mma_sync(c[n], a, b, c[n]);
        }
    }
    __syncthreads();

    #pragma unroll
    for (int n = 0; n < 2; n++)
        wmma::store_matrix_sync(sC + rt * 16 * 64 + (cp + n) * 16, c[n], 64, wmma::mem_row_major);
    __syncthreads();

    #pragma unroll
    for (int i = tid; i < 64 * 8; i += 256) {
        int r = i >> 3, c8 = i & 7;
        int gr = m0 + r;
        if (gr < N_NODES) {
            float s = g_dis[gr];
            const float* p = sC + r * 64 + c8 * 8;
            __half2 h0 = __floats2half2_rn(p[0] * s, p[1] * s);
            __half2 h1 = __floats2half2_rn(p[2] * s, p[3] * s);
            __half2 h2 = __floats2half2_rn(p[4] * s, p[5] * s);
            __half2 h3 = __floats2half2_rn(p[6] * s, p[7] * s);
            *(uint4*)(Y + gr * 64 + c8 * 8) =
                make_uint4(*(unsigned*)&h0, *(unsigned*)&h1, *(unsigned*)&h2, *(unsigned*)&h3);
        }
    }
}

// ---------------- layer-1 aggregation: warp per node, half-warp split -------
// hh pre-scaled; h1 = fp16(relu( dis_i*(sum_e hhs[r_e] + hhs_i) + b1 ))
// 16 lanes x uint4 cover 128 ch; the two half-warps process 2 edges at once.
__global__ void k_agg1(const float* __restrict__ b1) {
    int w = (blockIdx.x * blockDim.x + threadIdx.x) >> 5;
    if (w >= N_NODES) return;
    int lane = threadIdx.x & 31;
    int half = lane >> 4, sub = lane & 15;
    float4 bbA = ((const float4*)b1)[sub * 2];
    float4 bbB = ((const float4*)b1)[sub * 2 + 1];

    cudaGridDependencySynchronize();   // wait for gemm1's hh/dis (cnt from fill)

    int n_edges = g_cnt[w]; if (n_edges > CAP) n_edges = CAP;
    const int* bkt = g_bkt + w * CAP;
    const uint4* hh4 = (const uint4*)g_hh;   // 16 uint4 per row
    float acc[8];
    #pragma unroll
    for (int q = 0; q < 8; q++) acc[q] = 0.f;

    for (int base = 0; base < n_edges; base += 32) {
        int n = n_edges - base; if (n > 32) n = 32;
        int ed = (base + lane < n_edges) ? bkt[base + lane] : 0;
        int j = 0;
        for (; j + 8 <= n; j += 8) {
            uint4 v[4];
            #pragma unroll
            for (int u = 0; u < 4; u++) {
                int idx = __shfl_sync(0xffffffffu, ed, j + 2 * u + half);
                v[u] = hh4[idx * 16 + sub];
            }
            #pragma unroll
            for (int q = 0; q < 4; q++) {
                __half2 a = __hadd2(((const __half2*)&v[0])[q], ((const __half2*)&v[1])[q]);
                __half2 b = __hadd2(((const __half2*)&v[2])[q], ((const __half2*)&v[3])[q]);
                float2 f = __half22float2(__hadd2(a, b));
                acc[2 * q]     += f.x;
                acc[2 * q + 1] += f.y;
            }
        }
        for (; j < n; j += 2) {
            int jj = j + half;                       // jj <= n <= 31 here
            int idx = __shfl_sync(0xffffffffu, ed, jj & 31);
            uint4 v = make_uint4(0, 0, 0, 0);
            if (jj < n) v = hh4[idx * 16 + sub];
            #pragma unroll
            for (int q = 0; q < 4; q++) {
                float2 f = __half22float2(((const __half2*)&v)[q]);
                acc[2 * q]     += f.x;
                acc[2 * q + 1] += f.y;
            }
        }
    }
    // merge the two half-warps (same channels live in lane and lane^16)
    #pragma unroll
    for (int q = 0; q < 8; q++)
        acc[q] += __shfl_xor_sync(0xffffffffu, acc[q], 16);

    if (half == 0) {
        float di = g_dis[w];
        uint4 vs = hh4[w * 16 + sub];           // hhs_i (pre-scaled)
        float o[8];
        #pragma unroll
        for (int q = 0; q < 4; q++) {
            float2 s = __half22float2(((const __half2*)&vs)[q]);
            o[2 * q]     = acc[2 * q] + s.x;
            o[2 * q + 1] = acc[2 * q + 1] + s.y;
        }
        float r0 = fmaxf(fmaf(o[0], di, bbA.x), 0.f);
        float r1 = fmaxf(fmaf(o[1], di, bbA.y), 0.f);
        float r2 = fmaxf(fmaf(o[2], di, bbA.z), 0.f);
        float r3 = fmaxf(fmaf(o[3], di, bbA.w), 0.f);
        float r4 = fmaxf(fmaf(o[4], di, bbB.x), 0.f);
        float r5 = fmaxf(fmaf(o[5], di, bbB.y), 0.f);
        float r6 = fmaxf(fmaf(o[6], di, bbB.z), 0.f);
        float r7 = fmaxf(fmaf(o[7], di, bbB.w), 0.f);
        __half2 h0 = __floats2half2_rn(r0, r1);
        __half2 h1 = __floats2half2_rn(r2, r3);
        __half2 h2 = __floats2half2_rn(r4, r5);
        __half2 h3 = __floats2half2_rn(r6, r7);
        ((uint4*)g_h1)[w * 16 + sub] =
            make_uint4(*(unsigned*)&h0, *(unsigned*)&h1, *(unsigned*)&h2, *(unsigned*)&h3);
    }
}

// ---------------- layer-2 aggregation: warp per node, half-warp split -------
// zh pre-scaled; zfh = fp16( dis_i*(sum_e zh[r_e] + zh_i) + b2 )
// 16 lanes x uint2 cover 64 ch; two half-warps process 2 edges at once.
__global__ void k_agg2(const float* __restrict__ b2) {
    int w = (blockIdx.x * blockDim.x + threadIdx.x) >> 5;
    if (w >= N_NODES) return;
    int lane = threadIdx.x & 31;
    int half = lane >> 4, sub = lane & 15;
    int n_edges = g_cnt[w]; if (n_edges > CAP) n_edges = CAP;
    const int* bkt = g_bkt + w * CAP;
    float4 bb = ((const float4*)b2)[sub];

    cudaGridDependencySynchronize();   // wait for gemm2's zh

    const uint2* zh2 = (const uint2*)g_zh;   // 16 uint2 per row
    float acc[4];
    #pragma unroll
    for (int q = 0; q < 4; q++) acc[q] = 0.f;

    for (int base = 0; base < n_edges; base += 32) {
        int n = n_edges - base; if (n > 32) n = 32;
        int ed = (base + lane < n_edges) ? bkt[base + lane] : 0;
        int j = 0;
        for (; j + 8 <= n; j += 8) {
            uint2 v[4];
            #pragma unroll
            for (int u = 0; u < 4; u++) {
                int idx = __shfl_sync(0xffffffffu, ed, j + 2 * u + half);
                v[u] = zh2[idx * 16 + sub];
            }
            #pragma unroll
            for (int q = 0; q < 2; q++) {
                __half2 a = __hadd2(((const __half2*)&v[0])[q], ((const __half2*)&v[1])[q]);
                __half2 b = __hadd2(((const __half2*)&v[2])[q], ((const __half2*)&v[3])[q]);
                float2 f = __half22float2(__hadd2(a, b));
                acc[2 * q]     += f.x;
                acc[2 * q + 1] += f.y;
            }
        }
        for (; j < n; j += 2) {
            int jj = j + half;
            int idx = __shfl_sync(0xffffffffu, ed, jj & 31);
            uint2 v = make_uint2(0, 0);
            if (jj < n) v = zh2[idx * 16 + sub];
            #pragma unroll
            for (int q = 0; q < 2; q++) {
                float2 f = __half22float2(((const __half2*)&v)[q]);
                acc[2 * q]     += f.x;
                acc[2 * q + 1] += f.y;
            }
        }
    }
    #pragma unroll
    for (int q = 0; q < 4; q++)
        acc[q] += __shfl_xor_sync(0xffffffffu, acc[q], 16);

    if (half == 0) {
        float di = g_dis[w];
        uint2 vs = zh2[w * 16 + sub];
        float2 s0 = __half22float2(*(const __half2*)&vs.x);
        float2 s1 = __half22float2(*(const __half2*)&vs.y);
        float r0 = fmaf(acc[0] + s0.x, di, bb.x);
        float r1 = fmaf(acc[1] + s0.y, di, bb.y);
        float r2 = fmaf(acc[2] + s1.x, di, bb.z);
        float r3 = fmaf(acc[3] + s1.y, di, bb.w);
        __half2 o0 = __floats2half2_rn(r0, r1);
        __half2 o1 = __floats2half2_rn(r2, r3);
        ((uint2*)g_zfh)[w * 16 + sub] = make_uint2(*(unsigned*)&o0, *(unsigned*)&o1);
    }
}

// ---------------- decode: 16-lane group per label edge (fp16 zf) ------------
__global__ void k_decode(const int* __restrict__ src, const int* __restrict__ dst,
                         float* __restrict__ out) {
    int t = blockIdx.x * blockDim.x + threadIdx.x;
    int e = t >> 4;
    int sub = t & 15;
    int s = 0, d = 0;
    if (e < N_LABEL) { s = __ldg(src + e); d = __ldg(dst + e); }

    cudaGridDependencySynchronize();   // wait for agg2's zfh (and its g_cnt reads)

    if (t < N_NODES) g_cnt[t] = 0;     // restore invariant for next replay
    if (e >= N_LABEL) return;
    const uint2* z2 = (const uint2*)g_zfh;    // 4 fp16 ch per sub-lane
    uint2 av = z2[s * 16 + sub];
    uint2 bv = z2[d * 16 + sub];
    float2 a0 = __half22float2(*(const __half2*)&av.x);
    float2 a1 = __half22float2(*(const __half2*)&av.y);
    float2 b0 = __half22float2(*(const __half2*)&bv.x);
    float2 b1 = __half22float2(*(const __half2*)&bv.y);
    float p = a0.x * b0.x + a0.y * b0.y + a1.x * b1.x + a1.y * b1.y;
    p += __shfl_xor_sync(0xffffffffu, p, 8, 16);
    p += __shfl_xor_sync(0xffffffffu, p, 4, 16);
    p += __shfl_xor_sync(0xffffffffu, p, 2, 16);
    p += __shfl_xor_sync(0xffffffffu, p, 1, 16);
    if (sub == 0) out[e] = p;
}

// ---------------- launch ----------------------------------------------------
extern "C" void kernel_launch(void* const* d_in, const int* in_sizes, int n_in,
                              void* d_out, int out_size) {
    const float* x  = (const float*)d_in[0];
    const float* W1 = (const float*)d_in[1];
    const float* b1 = (const float*)d_in[2];
    const float* W2 = (const float*)d_in[3];
    const float* b2 = (const float*)d_in[4];
    const int* edge_index = (const int*)d_in[5];
    const int* edge_label = (const int*)d_in[6];
    float* out = (float*)d_out;

    const int* erow = edge_index;
    const int* ecol = edge_index + N_EDGES;
    const int* lsrc = edge_label;
    const int* ldst = edge_label + N_LABEL;

    __half *phh, *ph1, *pzh;
    cudaGetSymbolAddress((void**)&phh, g_hh);
    cudaGetSymbolAddress((void**)&ph1, g_h1);
    cudaGetSymbolAddress((void**)&pzh, g_zh);

    const int smem1 = 34816 * 2;          // 69632
    const int smem2 = 17408 + 18432;      // 35840
    cudaFuncSetAttribute(k_gemm1, cudaFuncAttributeMaxDynamicSharedMemorySize, smem1);
    cudaFuncSetAttribute(k_gemm2, cudaFuncAttributeMaxDynamicSharedMemorySize, smem2);

    const int gemm1_grid = (N_NODES + 127) / 128;      // 391
    const int gemm2_grid = (N_NODES + 63) / 64;        // 782
    const int fill_grid  = (N_EDGES / 8 + 255) / 256;  // 391
    const int agg_grid   = (N_NODES * 32 + 255) / 256; // 6250
    const int dec_grid   = (N_LABEL * 16 + 255) / 256; // 12500

    k_fill_direct<<<fill_grid, 256>>>((const int4*)erow, (const int4*)ecol);
    launch_pdl(k_gemm1,  dim3(gemm1_grid), dim3(256), (size_t)smem1, x, W1, phh);
    launch_pdl(k_agg1,   dim3(agg_grid),   dim3(256), (size_t)0, b1);
    launch_pdl(k_gemm2,  dim3(gemm2_grid), dim3(256), (size_t)smem2, (const __half*)ph1, W2, pzh);
    launch_pdl(k_agg2,   dim3(agg_grid),   dim3(256), (size_t)0, b2);
    launch_pdl(k_decode, dim3(dec_grid),   dim3(256), (size_t)0, lsrc, ldst, out);
}

// round 16
// speedup vs baseline: 1.0054x; 1.0054x over previous
#include <cuda_runtime.h>
#include <cuda_fp16.h>
#include <mma.h>

using namespace nvcuda;

#define N_NODES 50000
#define N_EDGES 800000
#define N_LABEL 200000
#define CAP 128            // bucket capacity per node (max deg ~40 for this data)

// ---------------- scratch (device globals; no allocation allowed) ----------
__device__ int    g_cnt[N_NODES];        // zero at load; re-zeroed by decode
__device__ float  g_dis[N_NODES];        // (deg+1)^-1/2 (written by gemm1 epilogue)
__device__ __align__(16) int    g_bkt[N_NODES * CAP];  // per-node edge buckets
__device__ __align__(16) __half g_hh[N_NODES * 128];   // fp16((x@W1) * dis[row])
__device__ __align__(16) __half g_h1[N_NODES * 128];   // relu layer-1 output, fp16
__device__ __align__(16) __half g_zh[N_NODES * 64];    // (h1 @ W2)*dis, fp16
__device__ __align__(16) __half g_zfh[N_NODES * 64];   // final embeddings, fp16

// ---------------- PDL launcher with plain-launch fallback -------------------
template <typename K, typename... A>
static inline void launch_pdl(K kern, dim3 grid, dim3 block, size_t smem, A... args) {
    cudaLaunchConfig_t cfg = {};
    cfg.gridDim = grid; cfg.blockDim = block; cfg.dynamicSmemBytes = smem; cfg.stream = 0;
    cudaLaunchAttribute at[1];
    at[0].id = cudaLaunchAttributeProgrammaticStreamSerialization;
    at[0].val.programmaticStreamSerializationAllowed = 1;
    cfg.attrs = at; cfg.numAttrs = 1;
    if (cudaLaunchKernelEx(&cfg, kern, args...) != cudaSuccess) {
        void* pa[] = { (void*)&args... };
        cudaLaunchKernel((const void*)kern, grid, block, pa, smem, 0);
    }
}

// ---------------- direct bucket fill (8 edges/thread) -----------------------
__global__ void k_fill_direct(const int4* __restrict__ row4,
                              const int4* __restrict__ col4) {
    int i = blockIdx.x * blockDim.x + threadIdx.x;
    if (i >= N_EDGES / 8) return;
    int4 r0 = row4[2 * i], r1 = row4[2 * i + 1];
    int4 c0 = col4[2 * i], c1 = col4[2 * i + 1];
    int p0 = atomicAdd(&g_cnt[c0.x], 1);
    int p1 = atomicAdd(&g_cnt[c0.y], 1);
    int p2 = atomicAdd(&g_cnt[c0.z], 1);
    int p3 = atomicAdd(&g_cnt[c0.w], 1);
    int p4 = atomicAdd(&g_cnt[c1.x], 1);
    int p5 = atomicAdd(&g_cnt[c1.y], 1);
    int p6 = atomicAdd(&g_cnt[c1.z], 1);
    int p7 = atomicAdd(&g_cnt[c1.w], 1);
    if (p0 < CAP) g_bkt[c0.x * CAP + p0] = r0.x;
    if (p1 < CAP) g_bkt[c0.y * CAP + p1] = r0.y;
    if (p2 < CAP) g_bkt[c0.z * CAP + p2] = r0.z;
    if (p3 < CAP) g_bkt[c0.w * CAP + p3] = r0.w;
    if (p4 < CAP) g_bkt[c1.x * CAP + p4] = r1.x;
    if (p5 < CAP) g_bkt[c1.y * CAP + p5] = r1.y;
    if (p6 < CAP) g_bkt[c1.z * CAP + p6] = r1.z;
    if (p7 < CAP) g_bkt[c1.w * CAP + p7] = r1.w;
}

// ---------------- GEMM1 (tensor): Hh = fp16((X @ W1) * dis[row]) ------------
__global__ __launch_bounds__(256) void k_gemm1(const float* __restrict__ X,
                                               const float* __restrict__ W,
                                               __half* __restrict__ Y) {
    constexpr int LDA = 136, LDB = 136;
    extern __shared__ __align__(32) char smem[];
    __half* sA = (__half*)smem;                    // 128*136*2 = 34816
    __half* sB = (__half*)(smem + 34816);          // 128*136*2 = 34816
    float*  sC = (float*)smem;                     // 128*128*4 = 65536 (alias)

    const int tid = threadIdx.x;
    const int wid = tid >> 5;
    const int m0  = blockIdx.x * 128;

    #pragma unroll
    for (int i = tid; i < 128 * 32; i += 256) {
        int r = i >> 5, c4 = i & 31;
        int gr = m0 + r;
        float4 v = (gr < N_NODES) ? ((const float4*)X)[gr * 32 + c4]
                                  : make_float4(0.f, 0.f, 0.f, 0.f);
        __half2 a = __floats2half2_rn(v.x, v.y);
        __half2 b = __floats2half2_rn(v.z, v.w);
        *(uint2*)(sA + r * LDA + c4 * 4) = make_uint2(*(unsigned*)&a, *(unsigned*)&b);
    }
    #pragma unroll
    for (int i = tid; i < 128 * 32; i += 256) {
        int r = i >> 5, c4 = i & 31;
        float4 v = ((const float4*)W)[r * 32 + c4];
        __half2 a = __floats2half2_rn(v.x, v.y);
        __half2 b = __floats2half2_rn(v.z, v.w);
        *(uint2*)(sB + r * LDB + c4 * 4) = make_uint2(*(unsigned*)&a, *(unsigned*)&b);
    }
    __syncthreads();

    wmma::fragment<wmma::accumulator, 16, 16, 16, float> c[8];
    #pragma unroll
    for (int n = 0; n < 8; n++) wmma::fill_fragment(c[n], 0.0f);

    #pragma unroll
    for (int k0 = 0; k0 < 8; k0++) {
        wmma::fragment<wmma::matrix_a, 16, 16, 16, __half, wmma::row_major> a;
        wmma::load_matrix_sync(a, sA + wid * 16 * LDA + k0 * 16, LDA);
        #pragma unroll
        for (int n = 0; n < 8; n++) {
            wmma::fragment<wmma::matrix_b, 16, 16, 16, __half, wmma::row_major> b;
            wmma::load_matrix_sync(b, sB + k0 * 16 * LDB + n * 16, LDB);
            wmma::mma_sync(c[n], a, b, c[n]);
        }
    }
    __syncthreads();

    #pragma unroll
    for (int n = 0; n < 8; n++)
        wmma::store_matrix_sync(sC + wid * 16 * 128 + n * 16, c[n], 128, wmma::mem_row_major);

    cudaGridDependencySynchronize();   // fill done -> g_cnt valid
    __syncthreads();

    #pragma unroll
    for (int i = tid; i < 128 * 16; i += 256) {
        int r = i >> 4, c8 = i & 15;
        int gr = m0 + r;
        if (gr < N_NODES) {
            float s = rsqrtf((float)g_cnt[gr] + 1.0f);
            if (c8 == 0) g_dis[gr] = s;
            const float* p = sC + r * 128 + c8 * 8;
            __half2 h0 = __floats2half2_rn(p[0] * s, p[1] * s);
            __half2 h1 = __floats2half2_rn(p[2] * s, p[3] * s);
            __half2 h2 = __floats2half2_rn(p[4] * s, p[5] * s);
            __half2 h3 = __floats2half2_rn(p[6] * s, p[7] * s);
            *(uint4*)(Y + gr * 128 + c8 * 8) =
                make_uint4(*(unsigned*)&h0, *(unsigned*)&h1, *(unsigned*)&h2, *(unsigned*)&h3);
        }
    }
}

// ---------------- GEMM2 (tensor): Zh = fp16((H1 @ W2) * dis[row]) -----------
__global__ __launch_bounds__(256) void k_gemm2(const __half* __restrict__ X,
                                               const float* __restrict__ W,
                                               __half* __restrict__ Y) {
    constexpr int LDA = 136, LDB = 72;
    extern __shared__ __align__(32) char smem[];
    __half* sA = (__half*)smem;                    // 64*136*2  = 17408
    __half* sB = (__half*)(smem + 17408);          // 128*72*2  = 18432
    float*  sC = (float*)smem;                     // 64*64*4   = 16384 (alias)

    const int tid = threadIdx.x;
    const int wid = tid >> 5;
    const int m0  = blockIdx.x * 64;

    #pragma unroll
    for (int i = tid; i < 128 * 16; i += 256) {
        int r = i >> 4, c4 = i & 15;
        float4 v = ((const float4*)W)[r * 16 + c4];
        __half2 a = __floats2half2_rn(v.x, v.y);
        __half2 b = __floats2half2_rn(v.z, v.w);
        *(uint2*)(sB + r * LDB + c4 * 4) = make_uint2(*(unsigned*)&a, *(unsigned*)&b);
    }

    cudaGridDependencySynchronize();   // wait for agg1's h1

    #pragma unroll
    for (int i = tid; i < 64 * 16; i += 256) {
        int r = i >> 4, c8 = i & 15;
        int gr = m0 + r;
        uint4 v = (gr < N_NODES) ? ((const uint4*)X)[gr * 16 + c8]
                                 : make_uint4(0, 0, 0, 0);
        *(uint4*)(sA + r * LDA + c8 * 8) = v;
    }
    __syncthreads();

    const int rt = wid >> 1;            // 0..3 row tile
    const int cp = (wid & 1) * 2;       // col tiles cp, cp+1

    wmma::fragment<wmma::accumulator, 16, 16, 16, float> c[2];
    #pragma unroll
    for (int n = 0; n < 2; n++) wmma::fill_fragment(c[n], 0.0f);

    #pragma unroll
    for (int k0 = 0; k0 < 8; k0++) {
        wmma::fragment<wmma::matrix_a, 16, 16, 16, __half, wmma::row_major> a;
        wmma::load_matrix_sync(a, sA + rt * 16 * LDA + k0 * 16, LDA);
        #pragma unroll
        for (int n = 0; n < 2; n++) {
            wmma::fragment<wmma::matrix_b, 16, 16, 16, __half, wmma::row_major> b;
            wmma::load_matrix_sync(b, sB + k0 * 16 * LDB + (cp + n) * 16, LDB);
            wmma::mma_sync(c[n], a, b, c[n]);
        }
    }
    __syncthreads();

    #pragma unroll
    for (int n = 0; n < 2; n++)
        wmma::store_matrix_sync(sC + rt * 16 * 64 + (cp + n) * 16, c[n], 64, wmma::mem_row_major);
    __syncthreads();

    #pragma unroll
    for (int i = tid; i < 64 * 8; i += 256) {
        int r = i >> 3, c8 = i & 7;
        int gr = m0 + r;
        if (gr < N_NODES) {
            float s = g_dis[gr];
            const float* p = sC + r * 64 + c8 * 8;
            __half2 h0 = __floats2half2_rn(p[0] * s, p[1] * s);
            __half2 h1 = __floats2half2_rn(p[2] * s, p[3] * s);
            __half2 h2 = __floats2half2_rn(p[4] * s, p[5] * s);
            __half2 h3 = __floats2half2_rn(p[6] * s, p[7] * s);
            *(uint4*)(Y + gr * 64 + c8 * 8) =
                make_uint4(*(unsigned*)&h0, *(unsigned*)&h1, *(unsigned*)&h2, *(unsigned*)&h3);
        }
    }
}

// ---------------- layer-1 aggregation: warp per node, 128 ch ----------------
// hh pre-scaled; h1 = fp16(relu( dis_i*(sum_e hhs[r_e] + hhs_i) + b1 ))
__global__ void k_agg1(const float* __restrict__ b1) {
    int w = (blockIdx.x * blockDim.x + threadIdx.x) >> 5;
    if (w >= N_NODES) return;
    int lane = threadIdx.x & 31;
    float4 bb = ((const float4*)b1)[lane];

    cudaGridDependencySynchronize();   // wait for gemm1's hh/dis (cnt from fill)

    int n_edges = g_cnt[w]; if (n_edges > CAP) n_edges = CAP;
    const int* bkt = g_bkt + w * CAP;
    const uint2* hh = (const uint2*)g_hh;   // 4 fp16 ch per lane
    float4 acc = make_float4(0.f, 0.f, 0.f, 0.f);

    for (int base = 0; base < n_edges; base += 32) {
        int n = n_edges - base; if (n > 32) n = 32;
        int ed = (base + lane < n_edges) ? bkt[base + lane] : 0;
        int j = 0;
        for (; j + 8 <= n; j += 8) {
            int r[8]; uint2 v[8];
            #pragma unroll
            for (int u = 0; u < 8; u++) r[u] = __shfl_sync(0xffffffffu, ed, j + u);
            #pragma unroll
            for (int u = 0; u < 8; u++) v[u] = hh[r[u] * 32 + lane];
            __half2 px[4], py[4];
            #pragma unroll
            for (int p = 0; p < 4; p++) {
                px[p] = __hadd2(*(const __half2*)&v[2*p].x, *(const __half2*)&v[2*p+1].x);
                py[p] = __hadd2(*(const __half2*)&v[2*p].y, *(const __half2*)&v[2*p+1].y);
            }
            __half2 qx0 = __hadd2(px[0], px[1]);
            __half2 qx1 = __hadd2(px[2], px[3]);
            __half2 qy0 = __hadd2(py[0], py[1]);
            __half2 qy1 = __hadd2(py[2], py[3]);
            float2 f0 = __half22float2(qx0), f1 = __half22float2(qx1);
            float2 g0 = __half22float2(qy0), g1 = __half22float2(qy1);
            acc.x += f0.x + f1.x; acc.y += f0.y + f1.y;
            acc.z += g0.x + g1.x; acc.w += g0.y + g1.y;
        }
        if (j + 4 <= n) {
            int r[4]; uint2 v[4];
            #pragma unroll
            for (int u = 0; u < 4; u++) r[u] = __shfl_sync(0xffffffffu, ed, j + u);
            #pragma unroll
            for (int u = 0; u < 4; u++) v[u] = hh[r[u] * 32 + lane];
            #pragma unroll
            for (int p = 0; p < 2; p++) {
                __half2 a = __hadd2(*(const __half2*)&v[2*p].x, *(const __half2*)&v[2*p+1].x);
                __half2 b = __hadd2(*(const __half2*)&v[2*p].y, *(const __half2*)&v[2*p+1].y);
                float2 f0 = __half22float2(a);
                float2 f1 = __half22float2(b);
                acc.x += f0.x; acc.y += f0.y; acc.z += f1.x; acc.w += f1.y;
            }
            j += 4;
        }
        for (; j < n; j++) {
            int r0 = __shfl_sync(0xffffffffu, ed, j);
            uint2 v0 = hh[r0 * 32 + lane];
            float2 f0 = __half22float2(*(const __half2*)&v0.x);
            float2 f1 = __half22float2(*(const __half2*)&v0.y);
            acc.x += f0.x; acc.y += f0.y; acc.z += f1.x; acc.w += f1.y;
        }
    }
    float di = g_dis[w];
    uint2 vs = hh[w * 32 + lane];           // hhs_i = dis_i * h_i (pre-scaled)
    float2 s0 = __half22float2(*(const __half2*)&vs.x);
    float2 s1 = __half22float2(*(const __half2*)&vs.y);
    acc.x += s0.x; acc.y += s0.y; acc.z += s1.x; acc.w += s1.y;
    float ox = fmaxf(fmaf(acc.x, di, bb.x), 0.f);
    float oy = fmaxf(fmaf(acc.y, di, bb.y), 0.f);
    float oz = fmaxf(fmaf(acc.z, di, bb.z), 0.f);
    float ow = fmaxf(fmaf(acc.w, di, bb.w), 0.f);
    __half2 o0 = __floats2half2_rn(ox, oy);
    __half2 o1 = __floats2half2_rn(oz, ow);
    *(uint2*)(g_h1 + w * 128 + lane * 4) = make_uint2(*(unsigned*)&o0, *(unsigned*)&o1);
}

// ---------------- layer-2 aggregation: warp per node, 64 ch, fp16 out -------
__global__ void k_agg2(const float* __restrict__ b2) {
    int w = (blockIdx.x * blockDim.x + threadIdx.x) >> 5;
    if (w >= N_NODES) return;
    int lane = threadIdx.x & 31;
    int n_edges = g_cnt[w]; if (n_edges > CAP) n_edges = CAP;
    const int* bkt = g_bkt + w * CAP;
    float2 bb = ((const float2*)b2)[lane];

    cudaGridDependencySynchronize();   // wait for gemm2's zh

    const unsigned* zh = (const unsigned*)g_zh;   // 2 fp16 ch per lane
    float2 acc = make_float2(0.f, 0.f);

    for (int base = 0; base < n_edges; base += 32) {
        int n = n_edges - base; if (n > 32) n = 32;
        int ed = (base + lane < n_edges) ? bkt[base + lane] : 0;
        int j = 0;
        for (; j + 8 <= n; j += 8) {
            int r[8]; unsigned v[8];
            #pragma unroll
            for (int u = 0; u < 8; u++) r[u] = __shfl_sync(0xffffffffu, ed, j + u);
            #pragma unroll
            for (int u = 0; u < 8; u++) v[u] = zh[r[u] * 32 + lane];
            __half2 p0 = __hadd2(*(const __half2*)&v[0], *(const __half2*)&v[1]);
            __half2 p1 = __hadd2(*(const __half2*)&v[2], *(const __half2*)&v[3]);
            __half2 p2 = __hadd2(*(const __half2*)&v[4], *(const __half2*)&v[5]);
            __half2 p3 = __hadd2(*(const __half2*)&v[6], *(const __half2*)&v[7]);
            __half2 q0 = __hadd2(p0, p1);
            __half2 q1 = __hadd2(p2, p3);
            float2 f = __half22float2(q0);
            float2 g = __half22float2(q1);
            acc.x += f.x + g.x; acc.y += f.y + g.y;
        }
        if (j + 4 <= n) {
            int r[4]; unsigned v[4];
            #pragma unroll
            for (int u = 0; u < 4; u++) r[u] = __shfl_sync(0xffffffffu, ed, j + u);
            #pragma unroll
            for (int u = 0; u < 4; u++) v[u] = zh[r[u] * 32 + lane];
            __half2 p0 = __hadd2(*(const __half2*)&v[0], *(const __half2*)&v[1]);
            __half2 p1 = __hadd2(*(const __half2*)&v[2], *(const __half2*)&v[3]);
            float2 f = __half22float2(p0);
            float2 g = __half22float2(p1);
            acc.x += f.x + g.x; acc.y += f.y + g.y;
            j += 4;
        }
        for (; j < n; j++) {
            int r0 = __shfl_sync(0xffffffffu, ed, j);
            unsigned v0 = zh[r0 * 32 + lane];
            float2 f = __half22float2(*(const __half2*)&v0);
            acc.x += f.x; acc.y += f.y;
        }
    }
    float di = g_dis[w];
    unsigned vs = zh[w * 32 + lane];
    float2 zs = __half22float2(*(const __half2*)&vs);
    float ox = fmaf(acc.x + zs.x, di, bb.x);
    float oy = fmaf(acc.y + zs.y, di, bb.y);
    __half2 o = __floats2half2_rn(ox, oy);
    ((unsigned*)g_zfh)[w * 32 + lane] = *(unsigned*)&o;
}

// ---------------- decode: 16-lane group per label edge (fp16 zf) ------------
__global__ void k_decode(const int* __restrict__ src, const int* __restrict__ dst,
                         float* __restrict__ out) {
    int t = blockIdx.x * blockDim.x + threadIdx.x;
    int e = t >> 4;
    int sub = t & 15;
    int s = 0, d = 0;
    if (e < N_LABEL) { s = __ldg(src + e); d = __ldg(dst + e); }

    cudaGridDependencySynchronize();   // wait for agg2's zfh (and its g_cnt reads)

    if (t < N_NODES) g_cnt[t] = 0;     // restore invariant for next replay
    if (e >= N_LABEL) return;
    const uint2* z2 = (const uint2*)g_zfh;    // 4 fp16 ch per sub-lane
    uint2 av = z2[s * 16 + sub];
    uint2 bv = z2[d * 16 + sub];
    float2 a0 = __half22float2(*(const __half2*)&av.x);
    float2 a1 = __half22float2(*(const __half2*)&av.y);
    float2 b0 = __half22float2(*(const __half2*)&bv.x);
    float2 b1 = __half22float2(*(const __half2*)&bv.y);
    float p = a0.x * b0.x + a0.y * b0.y + a1.x * b1.x + a1.y * b1.y;
    p += __shfl_xor_sync(0xffffffffu, p, 8, 16);
    p += __shfl_xor_sync(0xffffffffu, p, 4, 16);
    p += __shfl_xor_sync(0xffffffffu, p, 2, 16);
    p += __shfl_xor_sync(0xffffffffu, p, 1, 16);
    if (sub == 0) out[e] = p;
}

// ---------------- launch ----------------------------------------------------
extern "C" void kernel_launch(void* const* d_in, const int* in_sizes, int n_in,
                              void* d_out, int out_size) {
    const float* x  = (const float*)d_in[0];
    const float* W1 = (const float*)d_in[1];
    const float* b1 = (const float*)d_in[2];
    const float* W2 = (const float*)d_in[3];
    const float* b2 = (const float*)d_in[4];
    const int* edge_index = (const int*)d_in[5];
    const int* edge_label = (const int*)d_in[6];
    float* out = (float*)d_out;

    const int* erow = edge_index;
    const int* ecol = edge_index + N_EDGES;
    const int* lsrc = edge_label;
    const int* ldst = edge_label + N_LABEL;

    __half *phh, *ph1, *pzh;
    cudaGetSymbolAddress((void**)&phh, g_hh);
    cudaGetSymbolAddress((void**)&ph1, g_h1);
    cudaGetSymbolAddress((void**)&pzh, g_zh);

    const int smem1 = 34816 * 2;          // 69632
    const int smem2 = 17408 + 18432;      // 35840
    cudaFuncSetAttribute(k_gemm1, cudaFuncAttributeMaxDynamicSharedMemorySize, smem1);
    cudaFuncSetAttribute(k_gemm2, cudaFuncAttributeMaxDynamicSharedMemorySize, smem2);

    const int gemm1_grid = (N_NODES + 127) / 128;      // 391
    const int gemm2_grid = (N_NODES + 63) / 64;        // 782
    const int fill_grid  = (N_EDGES / 8 + 255) / 256;  // 391
    const int agg_grid   = (N_NODES * 32 + 511) / 512; // 3125 (512-thread blocks)
    const int dec_grid   = (N_LABEL * 16 + 511) / 512; // 6250 (512-thread blocks)

    k_fill_direct<<<fill_grid, 256>>>((const int4*)erow, (const int4*)ecol);
    launch_pdl(k_gemm1,  dim3(gemm1_grid), dim3(256), (size_t)smem1, x, W1, phh);
    launch_pdl(k_agg1,   dim3(agg_grid),   dim3(512), (size_t)0, b1);
    launch_pdl(k_gemm2,  dim3(gemm2_grid), dim3(256), (size_t)smem2, (const __half*)ph1, W2, pzh);
    launch_pdl(k_agg2,   dim3(agg_grid),   dim3(512), (size_t)0, b2);
    launch_pdl(k_decode, dim3(dec_grid),   dim3(512), (size_t)0, lsrc, ldst, out);
}

// round 17
// speedup vs baseline: 1.0423x; 1.0366x over previous
#include <cuda_runtime.h>
#include <cuda_fp16.h>
#include <mma.h>

using namespace nvcuda;

#define N_NODES 50000
#define N_EDGES 800000
#define N_LABEL 200000
#define CAP 128            // bucket capacity per node (max deg ~40 for this data)

// ---------------- scratch (device globals; no allocation allowed) ----------
__device__ int    g_cnt[N_NODES];        // zero at load; re-zeroed by decode
__device__ float  g_dis[N_NODES];        // (deg+1)^-1/2 (written by gemm1 epilogue)
__device__ __align__(16) int    g_bkt[N_NODES * CAP];  // per-node buckets: row*32
__device__ __align__(16) __half g_hh[N_NODES * 128];   // fp16((x@W1) * dis[row])
__device__ __align__(16) __half g_h1[N_NODES * 128];   // relu layer-1 output, fp16
__device__ __align__(16) __half g_zh[N_NODES * 64];    // (h1 @ W2)*dis, fp16
__device__ __align__(16) __half g_zfh[N_NODES * 64];   // final embeddings, fp16

// ---------------- PDL launcher with plain-launch fallback -------------------
template <typename K, typename... A>
static inline void launch_pdl(K kern, dim3 grid, dim3 block, size_t smem, A... args) {
    cudaLaunchConfig_t cfg = {};
    cfg.gridDim = grid; cfg.blockDim = block; cfg.dynamicSmemBytes = smem; cfg.stream = 0;
    cudaLaunchAttribute at[1];
    at[0].id = cudaLaunchAttributeProgrammaticStreamSerialization;
    at[0].val.programmaticStreamSerializationAllowed = 1;
    cfg.attrs = at; cfg.numAttrs = 1;
    if (cudaLaunchKernelEx(&cfg, kern, args...) != cudaSuccess) {
        void* pa[] = { (void*)&args... };
        cudaLaunchKernel((const void*)kern, grid, block, pa, smem, 0);
    }
}

// ---------------- direct bucket fill (8 edges/thread); stores row*32 --------
__global__ void k_fill_direct(const int4* __restrict__ row4,
                              const int4* __restrict__ col4) {
    int i = blockIdx.x * blockDim.x + threadIdx.x;
    if (i >= N_EDGES / 8) return;
    int4 r0 = row4[2 * i], r1 = row4[2 * i + 1];
    int4 c0 = col4[2 * i], c1 = col4[2 * i + 1];
    int p0 = atomicAdd(&g_cnt[c0.x], 1);
    int p1 = atomicAdd(&g_cnt[c0.y], 1);
    int p2 = atomicAdd(&g_cnt[c0.z], 1);
    int p3 = atomicAdd(&g_cnt[c0.w], 1);
    int p4 = atomicAdd(&g_cnt[c1.x], 1);
    int p5 = atomicAdd(&g_cnt[c1.y], 1);
    int p6 = atomicAdd(&g_cnt[c1.z], 1);
    int p7 = atomicAdd(&g_cnt[c1.w], 1);
    if (p0 < CAP) g_bkt[c0.x * CAP + p0] = r0.x << 5;
    if (p1 < CAP) g_bkt[c0.y * CAP + p1] = r0.y << 5;
    if (p2 < CAP) g_bkt[c0.z * CAP + p2] = r0.z << 5;
    if (p3 < CAP) g_bkt[c0.w * CAP + p3] = r0.w << 5;
    if (p4 < CAP) g_bkt[c1.x * CAP + p4] = r1.x << 5;
    if (p5 < CAP) g_bkt[c1.y * CAP + p5] = r1.y << 5;
    if (p6 < CAP) g_bkt[c1.z * CAP + p6] = r1.z << 5;
    if (p7 < CAP) g_bkt[c1.w * CAP + p7] = r1.w << 5;
}

// ---------------- GEMM1 (tensor): Hh = fp16((X @ W1) * dis[row]) ------------
__global__ __launch_bounds__(256) void k_gemm1(const float* __restrict__ X,
                                               const float* __restrict__ W,
                                               __half* __restrict__ Y) {
    constexpr int LDA = 136, LDB = 136;
    extern __shared__ __align__(32) char smem[];
    __half* sA = (__half*)smem;                    // 128*136*2 = 34816
    __half* sB = (__half*)(smem + 34816);          // 128*136*2 = 34816
    float*  sC = (float*)smem;                     // 128*128*4 = 65536 (alias)

    const int tid = threadIdx.x;
    const int wid = tid >> 5;
    const int m0  = blockIdx.x * 128;

    #pragma unroll
    for (int i = tid; i < 128 * 32; i += 256) {
        int r = i >> 5, c4 = i & 31;
        int gr = m0 + r;
        float4 v = (gr < N_NODES) ? ((const float4*)X)[gr * 32 + c4]
                                  : make_float4(0.f, 0.f, 0.f, 0.f);
        __half2 a = __floats2half2_rn(v.x, v.y);
        __half2 b = __floats2half2_rn(v.z, v.w);
        *(uint2*)(sA + r * LDA + c4 * 4) = make_uint2(*(unsigned*)&a, *(unsigned*)&b);
    }
    #pragma unroll
    for (int i = tid; i < 128 * 32; i += 256) {
        int r = i >> 5, c4 = i & 31;
        float4 v = ((const float4*)W)[r * 32 + c4];
        __half2 a = __floats2half2_rn(v.x, v.y);
        __half2 b = __floats2half2_rn(v.z, v.w);
        *(uint2*)(sB + r * LDB + c4 * 4) = make_uint2(*(unsigned*)&a, *(unsigned*)&b);
    }
    __syncthreads();

    wmma::fragment<wmma::accumulator, 16, 16, 16, float> c[8];
    #pragma unroll
    for (int n = 0; n < 8; n++) wmma::fill_fragment(c[n], 0.0f);

    #pragma unroll
    for (int k0 = 0; k0 < 8; k0++) {
        wmma::fragment<wmma::matrix_a, 16, 16, 16, __half, wmma::row_major> a;
        wmma::load_matrix_sync(a, sA + wid * 16 * LDA + k0 * 16, LDA);
        #pragma unroll
        for (int n = 0; n < 8; n++) {
            wmma::fragment<wmma::matrix_b, 16, 16, 16, __half, wmma::row_major> b;
            wmma::load_matrix_sync(b, sB + k0 * 16 * LDB + n * 16, LDB);
            wmma::mma_sync(c[n], a, b, c[n]);
        }
    }
    __syncthreads();

    #pragma unroll
    for (int n = 0; n < 8; n++)
        wmma::store_matrix_sync(sC + wid * 16 * 128 + n * 16, c[n], 128, wmma::mem_row_major);

    cudaGridDependencySynchronize();   // fill done -> g_cnt valid
    __syncthreads();

    #pragma unroll
    for (int i = tid; i < 128 * 16; i += 256) {
        int r = i >> 4, c8 = i & 15;
        int gr = m0 + r;
        if (gr < N_NODES) {
            float s = rsqrtf((float)g_cnt[gr] + 1.0f);
            if (c8 == 0) g_dis[gr] = s;
            const float* p = sC + r * 128 + c8 * 8;
            __half2 h0 = __floats2half2_rn(p[0] * s, p[1] * s);
            __half2 h1 = __floats2half2_rn(p[2] * s, p[3] * s);
            __half2 h2 = __floats2half2_rn(p[4] * s, p[5] * s);
            __half2 h3 = __floats2half2_rn(p[6] * s, p[7] * s);
            *(uint4*)(Y + gr * 128 + c8 * 8) =
                make_uint4(*(unsigned*)&h0, *(unsigned*)&h1, *(unsigned*)&h2, *(unsigned*)&h3);
        }
    }
}

// ---------------- GEMM2 (tensor): Zh = fp16((H1 @ W2) * dis[row]) -----------
__global__ __launch_bounds__(256) void k_gemm2(const __half* __restrict__ X,
                                               const float* __restrict__ W,
                                               __half* __restrict__ Y) {
    constexpr int LDA = 136, LDB = 72;
    extern __shared__ __align__(32) char smem[];
    __half* sA = (__half*)smem;                    // 64*136*2  = 17408
    __half* sB = (__half*)(smem + 17408);          // 128*72*2  = 18432
    float*  sC = (float*)smem;                     // 64*64*4   = 16384 (alias)

    const int tid = threadIdx.x;
    const int wid = tid >> 5;
    const int m0  = blockIdx.x * 64;

    #pragma unroll
    for (int i = tid; i < 128 * 16; i += 256) {
        int r = i >> 4, c4 = i & 15;
        float4 v = ((const float4*)W)[r * 16 + c4];
        __half2 a = __floats2half2_rn(v.x, v.y);
        __half2 b = __floats2half2_rn(v.z, v.w);
        *(uint2*)(sB + r * LDB + c4 * 4) = make_uint2(*(unsigned*)&a, *(unsigned*)&b);
    }

    cudaGridDependencySynchronize();   // wait for agg1's h1

    #pragma unroll
    for (int i = tid; i < 64 * 16; i += 256) {
        int r = i >> 4, c8 = i & 15;
        int gr = m0 + r;
        uint4 v = (gr < N_NODES) ? ((const uint4*)X)[gr * 16 + c8]
                                 : make_uint4(0, 0, 0, 0);
        *(uint4*)(sA + r * LDA + c8 * 8) = v;
    }
    __syncthreads();

    const int rt = wid >> 1;            // 0..3 row tile
    const int cp = (wid & 1) * 2;       // col tiles cp, cp+1

    wmma::fragment<wmma::accumulator, 16, 16, 16, float> c[2];
    #pragma unroll
    for (int n = 0; n < 2; n++) wmma::fill_fragment(c[n], 0.0f);

    #pragma unroll
    for (int k0 = 0; k0 < 8; k0++) {
        wmma::fragment<wmma::matrix_a, 16, 16, 16, __half, wmma::row_major> a;
        wmma::load_matrix_sync(a, sA + rt * 16 * LDA + k0 * 16, LDA);
        #pragma unroll
        for (int n = 0; n < 2; n++) {
            wmma::fragment<wmma::matrix_b, 16, 16, 16, __half, wmma::row_major> b;
            wmma::load_matrix_sync(b, sB + k0 * 16 * LDB + (cp + n) * 16, LDB);
            wmma::mma_sync(c[n], a, b, c[n]);
        }
    }
    __syncthreads();

    #pragma unroll
    for (int n = 0; n < 2; n++)
        wmma::store_matrix_sync(sC + rt * 16 * 64 + (cp + n) * 16, c[n], 64, wmma::mem_row_major);
    __syncthreads();

    #pragma unroll
    for (int i = tid; i < 64 * 8; i += 256) {
        int r = i >> 3, c8 = i & 7;
        int gr = m0 + r;
        if (gr < N_NODES) {
            float s = g_dis[gr];
            const float* p = sC + r * 64 + c8 * 8;
            __half2 h0 = __floats2half2_rn(p[0] * s, p[1] * s);
            __half2 h1 = __floats2half2_rn(p[2] * s, p[3] * s);
            __half2 h2 = __floats2half2_rn(p[4] * s, p[5] * s);
            __half2 h3 = __floats2half2_rn(p[6] * s, p[7] * s);
            *(uint4*)(Y + gr * 64 + c8 * 8) =
                make_uint4(*(unsigned*)&h0, *(unsigned*)&h1, *(unsigned*)&h2, *(unsigned*)&h3);
        }
    }
}

// ---------------- layer-1 aggregation: warp per node, 128 ch ----------------
// hh pre-scaled; h1 = fp16(relu( dis_i*(sum_e hhs[r_e] + hhs_i) + b1 ))
// bucket entries are row*32: lane address = ed32 + lane (no IMAD).
__global__ void k_agg1(const float* __restrict__ b1) {
    int w = (blockIdx.x * blockDim.x + threadIdx.x) >> 5;
    if (w >= N_NODES) return;
    int lane = threadIdx.x & 31;
    float4 bb = ((const float4*)b1)[lane];

    cudaGridDependencySynchronize();   // wait for gemm1's hh/dis (cnt from fill)

    int n_edges = g_cnt[w]; if (n_edges > CAP) n_edges = CAP;
    const int* bkt = g_bkt + w * CAP;
    const uint2* hh = (const uint2*)g_hh;   // 4 fp16 ch per lane
    float4 acc = make_float4(0.f, 0.f, 0.f, 0.f);

    for (int base = 0; base < n_edges; base += 32) {
        int n = n_edges - base; if (n > 32) n = 32;
        int ed = (base + lane < n_edges) ? bkt[base + lane] : 0;
        int j = 0;
        for (; j + 8 <= n; j += 8) {
            int r[8]; uint2 v[8];
            #pragma unroll
            for (int u = 0; u < 8; u++) r[u] = __shfl_sync(0xffffffffu, ed, j + u);
            #pragma unroll
            for (int u = 0; u < 8; u++) v[u] = hh[r[u] + lane];
            __half2 px[4], py[4];
            #pragma unroll
            for (int p = 0; p < 4; p++) {
                px[p] = __hadd2(*(const __half2*)&v[2*p].x, *(const __half2*)&v[2*p+1].x);
                py[p] = __hadd2(*(const __half2*)&v[2*p].y, *(const __half2*)&v[2*p+1].y);
            }
            __half2 qx0 = __hadd2(px[0], px[1]);
            __half2 qx1 = __hadd2(px[2], px[3]);
            __half2 qy0 = __hadd2(py[0], py[1]);
            __half2 qy1 = __hadd2(py[2], py[3]);
            float2 f0 = __half22float2(qx0), f1 = __half22float2(qx1);
            float2 g0 = __half22float2(qy0), g1 = __half22float2(qy1);
            acc.x += f0.x + f1.x; acc.y += f0.y + f1.y;
            acc.z += g0.x + g1.x; acc.w += g0.y + g1.y;
        }
        if (j + 4 <= n) {
            int r[4]; uint2 v[4];
            #pragma unroll
            for (int u = 0; u < 4; u++) r[u] = __shfl_sync(0xffffffffu, ed, j + u);
            #pragma unroll
            for (int u = 0; u < 4; u++) v[u] = hh[r[u] + lane];
            #pragma unroll
            for (int p = 0; p < 2; p++) {
                __half2 a = __hadd2(*(const __half2*)&v[2*p].x, *(const __half2*)&v[2*p+1].x);
                __half2 b = __hadd2(*(const __half2*)&v[2*p].y, *(const __half2*)&v[2*p+1].y);
                float2 f0 = __half22float2(a);
                float2 f1 = __half22float2(b);
                acc.x += f0.x; acc.y += f0.y; acc.z += f1.x; acc.w += f1.y;
            }
            j += 4;
        }
        for (; j < n; j++) {
            int r0 = __shfl_sync(0xffffffffu, ed, j);
            uint2 v0 = hh[r0 + lane];
            float2 f0 = __half22float2(*(const __half2*)&v0.x);
            float2 f1 = __half22float2(*(const __half2*)&v0.y);
            acc.x += f0.x; acc.y += f0.y; acc.z += f1.x; acc.w += f1.y;
        }
    }
    float di = g_dis[w];
    uint2 vs = hh[w * 32 + lane];           // hhs_i = dis_i * h_i (pre-scaled)
    float2 s0 = __half22float2(*(const __half2*)&vs.x);
    float2 s1 = __half22float2(*(const __half2*)&vs.y);
    acc.x += s0.x; acc.y += s0.y; acc.z += s1.x; acc.w += s1.y;
    float ox = fmaxf(fmaf(acc.x, di, bb.x), 0.f);
    float oy = fmaxf(fmaf(acc.y, di, bb.y), 0.f);
    float oz = fmaxf(fmaf(acc.z, di, bb.z), 0.f);
    float ow = fmaxf(fmaf(acc.w, di, bb.w), 0.f);
    __half2 o0 = __floats2half2_rn(ox, oy);
    __half2 o1 = __floats2half2_rn(oz, ow);
    *(uint2*)(g_h1 + w * 128 + lane * 4) = make_uint2(*(unsigned*)&o0, *(unsigned*)&o1);
}

// ---------------- layer-2 aggregation: warp per node, 64 ch, fp16 out -------
// bucket entries are row*32: lane address = ed32 + lane (zh stride = 32 uints).
__global__ void k_agg2(const float* __restrict__ b2) {
    int w = (blockIdx.x * blockDim.x + threadIdx.x) >> 5;
    if (w >= N_NODES) return;
    int lane = threadIdx.x & 31;
    int n_edges = g_cnt[w]; if (n_edges > CAP) n_edges = CAP;
    const int* bkt = g_bkt + w * CAP;
    float2 bb = ((const float2*)b2)[lane];

    cudaGridDependencySynchronize();   // wait for gemm2's zh

    const unsigned* zh = (const unsigned*)g_zh;   // 2 fp16 ch per lane
    float2 acc = make_float2(0.f, 0.f);

    for (int base = 0; base < n_edges; base += 32) {
        int n = n_edges - base; if (n > 32) n = 32;
        int ed = (base + lane < n_edges) ? bkt[base + lane] : 0;
        int j = 0;
        for (; j + 8 <= n; j += 8) {
            int r[8]; unsigned v[8];
            #pragma unroll
            for (int u = 0; u < 8; u++) r[u] = __shfl_sync(0xffffffffu, ed, j + u);
            #pragma unroll
            for (int u = 0; u < 8; u++) v[u] = zh[r[u] + lane];
            __half2 p0 = __hadd2(*(const __half2*)&v[0], *(const __half2*)&v[1]);
            __half2 p1 = __hadd2(*(const __half2*)&v[2], *(const __half2*)&v[3]);
            __half2 p2 = __hadd2(*(const __half2*)&v[4], *(const __half2*)&v[5]);
            __half2 p3 = __hadd2(*(const __half2*)&v[6], *(const __half2*)&v[7]);
            __half2 q0 = __hadd2(p0, p1);
            __half2 q1 = __hadd2(p2, p3);
            float2 f = __half22float2(q0);
            float2 g = __half22float2(q1);
            acc.x += f.x + g.x; acc.y += f.y + g.y;
        }
        if (j + 4 <= n) {
            int r[4]; unsigned v[4];
            #pragma unroll
            for (int u = 0; u < 4; u++) r[u] = __shfl_sync(0xffffffffu, ed, j + u);
            #pragma unroll
            for (int u = 0; u < 4; u++) v[u] = zh[r[u] + lane];
            __half2 p0 = __hadd2(*(const __half2*)&v[0], *(const __half2*)&v[1]);
            __half2 p1 = __hadd2(*(const __half2*)&v[2], *(const __half2*)&v[3]);
            float2 f = __half22float2(p0);
            float2 g = __half22float2(p1);
            acc.x += f.x + g.x; acc.y += f.y + g.y;
            j += 4;
        }
        for (; j < n; j++) {
            int r0 = __shfl_sync(0xffffffffu, ed, j);
            unsigned v0 = zh[r0 + lane];
            float2 f = __half22float2(*(const __half2*)&v0);
            acc.x += f.x; acc.y += f.y;
        }
    }
    float di = g_dis[w];
    unsigned vs = zh[w * 32 + lane];
    float2 zs = __half22float2(*(const __half2*)&vs);
    float ox = fmaf(acc.x + zs.x, di, bb.x);
    float oy = fmaf(acc.y + zs.y, di, bb.y);
    __half2 o = __floats2half2_rn(ox, oy);
    ((unsigned*)g_zfh)[w * 32 + lane] = *(unsigned*)&o;
}

// ---------------- decode: 16-lane group per label edge (fp16 zf) ------------
__global__ void k_decode(const int* __restrict__ src, const int* __restrict__ dst,
                         float* __restrict__ out) {
    int t = blockIdx.x * blockDim.x + threadIdx.x;
    int e = t >> 4;
    int sub = t & 15;
    int s = 0, d = 0;
    if (e < N_LABEL) { s = __ldg(src + e); d = __ldg(dst + e); }

    cudaGridDependencySynchronize();   // wait for agg2's zfh (and its g_cnt reads)

    if (t < N_NODES) g_cnt[t] = 0;     // restore invariant for next replay
    if (e >= N_LABEL) return;
    const uint2* z2 = (const uint2*)g_zfh;    // 4 fp16 ch per sub-lane
    uint2 av = z2[s * 16 + sub];
    uint2 bv = z2[d * 16 + sub];
    float2 a0 = __half22float2(*(const __half2*)&av.x);
    float2 a1 = __half22float2(*(const __half2*)&av.y);
    float2 b0 = __half22float2(*(const __half2*)&bv.x);
    float2 b1 = __half22float2(*(const __half2*)&bv.y);
    float p = a0.x * b0.x + a0.y * b0.y + a1.x * b1.x + a1.y * b1.y;
    p += __shfl_xor_sync(0xffffffffu, p, 8, 16);
    p += __shfl_xor_sync(0xffffffffu, p, 4, 16);
    p += __shfl_xor_sync(0xffffffffu, p, 2, 16);
    p += __shfl_xor_sync(0xffffffffu, p, 1, 16);
    if (sub == 0) out[e] = p;
}

// ---------------- launch ----------------------------------------------------
extern "C" void kernel_launch(void* const* d_in, const int* in_sizes, int n_in,
                              void* d_out, int out_size) {
    const float* x  = (const float*)d_in[0];
    const float* W1 = (const float*)d_in[1];
    const float* b1 = (const float*)d_in[2];
    const float* W2 = (const float*)d_in[3];
    const float* b2 = (const float*)d_in[4];
    const int* edge_index = (const int*)d_in[5];
    const int* edge_label = (const int*)d_in[6];
    float* out = (float*)d_out;

    const int* erow = edge_index;
    const int* ecol = edge_index + N_EDGES;
    const int* lsrc = edge_label;
    const int* ldst = edge_label + N_LABEL;

    __half *phh, *ph1, *pzh;
    cudaGetSymbolAddress((void**)&phh, g_hh);
    cudaGetSymbolAddress((void**)&ph1, g_h1);
    cudaGetSymbolAddress((void**)&pzh, g_zh);

    const int smem1 = 34816 * 2;          // 69632
    const int smem2 = 17408 + 18432;      // 35840
    cudaFuncSetAttribute(k_gemm1, cudaFuncAttributeMaxDynamicSharedMemorySize, smem1);
    cudaFuncSetAttribute(k_gemm2, cudaFuncAttributeMaxDynamicSharedMemorySize, smem2);

    const int gemm1_grid = (N_NODES + 127) / 128;      // 391
    const int gemm2_grid = (N_NODES + 63) / 64;        // 782
    const int fill_grid  = (N_EDGES / 8 + 255) / 256;  // 391
    const int agg_grid   = (N_NODES * 32 + 255) / 256; // 6250
    const int dec_grid   = (N_LABEL * 16 + 255) / 256; // 12500

    k_fill_direct<<<fill_grid, 256>>>((const int4*)erow, (const int4*)ecol);
    launch_pdl(k_gemm1,  dim3(gemm1_grid), dim3(256), (size_t)smem1, x, W1, phh);
    launch_pdl(k_agg1,   dim3(agg_grid),   dim3(256), (size_t)0, b1);
    launch_pdl(k_gemm2,  dim3(gemm2_grid), dim3(256), (size_t)smem2, (const __half*)ph1, W2, pzh);
    launch_pdl(k_agg2,   dim3(agg_grid),   dim3(256), (size_t)0, b2);
    launch_pdl(k_decode, dim3(dec_grid),   dim3(256), (size_t)0, lsrc, ldst, out);
}